// round 14
// baseline (speedup 1.0000x reference)
#include <cuda_runtime.h>
#include <cuda_fp16.h>
#include <math.h>
#include <stdint.h>
#include <string.h>

#define BATCH 4
#define SEQ 2048
#define DM 768
#define NH 12
#define DH 64
#define ROWS (BATCH*SEQ)

__device__ __half g_xh [(size_t)ROWS*DM];
__device__ __half g_wqh[(size_t)NH*DM*DH];
__device__ __half g_wkh[(size_t)NH*DM*DH];
__device__ __half g_wvh[(size_t)NH*DM*DH];
__device__ __half g_woh[(size_t)DM*DM];
__device__ __half g_q[(size_t)BATCH*NH*SEQ*DH];  // pre-scaled by 0.125*log2e
__device__ __half g_k[(size_t)BATCH*NH*SEQ*DH];
__device__ __half g_v[(size_t)BATCH*NH*SEQ*DH];
__device__ __half g_zh[(size_t)ROWS*DM];

#define QSC 0.1803368801111154f  /* 0.125 * log2(e) */

__device__ __forceinline__ float ex2f(float x) {
    float y; asm("ex2.approx.f32 %0, %1;" : "=f"(y) : "f"(x)); return y;
}
__device__ __forceinline__ uint32_t h2u(__half2 h) {
    uint32_t u;
    memcpy(&u, &h, 4);
    return u;
}
__device__ __forceinline__ void mma16(float* d, const uint32_t* a, const uint32_t* b) {
    asm volatile(
        "mma.sync.aligned.m16n8k16.row.col.f32.f16.f16.f32 "
        "{%0,%1,%2,%3}, {%4,%5,%6,%7}, {%8,%9}, {%0,%1,%2,%3};\n"
        : "+f"(d[0]), "+f"(d[1]), "+f"(d[2]), "+f"(d[3])
        : "r"(a[0]), "r"(a[1]), "r"(a[2]), "r"(a[3]), "r"(b[0]), "r"(b[1]));
}
__device__ __forceinline__ void ldsm4(uint32_t* r, uint32_t addr) {
    asm volatile("ldmatrix.sync.aligned.m8n8.x4.shared.b16 {%0,%1,%2,%3}, [%4];"
        : "=r"(r[0]), "=r"(r[1]), "=r"(r[2]), "=r"(r[3]) : "r"(addr));
}
__device__ __forceinline__ void ldsm4t(uint32_t* r, uint32_t addr) {
    asm volatile("ldmatrix.sync.aligned.m8n8.x4.trans.shared.b16 {%0,%1,%2,%3}, [%4];"
        : "=r"(r[0]), "=r"(r[1]), "=r"(r[2]), "=r"(r[3]) : "r"(addr));
}
__device__ __forceinline__ uint32_t su32(const void* p) {
    return (uint32_t)__cvta_generic_to_shared(p);
}
#define CPA(dst, src) asm volatile("cp.async.cg.shared.global [%0], [%1], 16;" :: "r"(dst), "l"(src))
#define CPC() asm volatile("cp.async.commit_group;")
#define CPW1() asm volatile("cp.async.wait_group 1;")
#define CPW0() asm volatile("cp.async.wait_group 0;")

// ---------------------------------------------------------------------------
// Prep: single fused fp32 -> fp16 conversion
// ---------------------------------------------------------------------------
#define NX4 (ROWS*DM/4)
#define NW4 (NH*DM*DH/4)
__global__ void __launch_bounds__(256) cvt_all_kernel(
    const float4* __restrict__ x,  const float4* __restrict__ wq,
    const float4* __restrict__ wk, const float4* __restrict__ wv,
    const float4* __restrict__ wo)
{
    int i = blockIdx.x * 256 + threadIdx.x;
    const float4* in;
    __half2* out;
    int j;
    if (i < NX4)                { in = x;  out = (__half2*)g_xh;  j = i; }
    else if (i < NX4 + NW4)     { in = wq; out = (__half2*)g_wqh; j = i - NX4; }
    else if (i < NX4 + 2*NW4)   { in = wk; out = (__half2*)g_wkh; j = i - NX4 - NW4; }
    else if (i < NX4 + 3*NW4)   { in = wv; out = (__half2*)g_wvh; j = i - NX4 - 2*NW4; }
    else if (i < NX4 + 4*NW4)   { in = wo; out = (__half2*)g_woh; j = i - NX4 - 3*NW4; }
    else return;
    float4 v = in[j];
    out[2*j]   = __floats2half2_rn(v.x, v.y);
    out[2*j+1] = __floats2half2_rn(v.z, v.w);
}
#define CVT_TOTAL (NX4 + 4*NW4)

// ===========================================================================
// GEMM: C[128x64], 128 threads (4 warps, 32x64 each), BK=64, 2-stage
// cp.async. smem 55.3KB -> 4 blocks/SM. (Unchanged from R13.)
// ===========================================================================
#define APh 72
#define BPh 72
#define A_STh (128*APh)
#define B_STh (64*BPh)
#define GEMM_SMEM ((2*A_STh + 2*B_STh) * 2)

template <typename FB>
__device__ __forceinline__ void gemm128x64(const __half* __restrict__ Ag,
                                           FB bsrc, int ntiles,
                                           __half* As, __half* Bs, float acc[2][8][4])
{
    const int tid = threadIdx.x;
    const int lane = tid & 31, wid = tid >> 5;
    const int lrow = lane & 15, lch = (lane >> 4) * 8;
    const int j8 = lane >> 3, i8 = lane & 7;

    auto load_tile = [&](int t, int s) {
        #pragma unroll
        for (int i = 0; i < 8; i++) {
            int id = tid + i * 128;
            int r = id >> 3, c8 = id & 7;
            CPA(su32(&As[s*A_STh + r*APh + c8*8]), Ag + (size_t)r * DM + t*64 + c8*8);
        }
        #pragma unroll
        for (int i = 0; i < 4; i++) {
            int id = tid + i * 128;
            int kr = id >> 3, c8 = id & 7;
            CPA(su32(&Bs[s*B_STh + kr*BPh + c8*8]), bsrc(t*64 + kr, c8));
        }
    };

    load_tile(0, 0); CPC();

    for (int t = 0; t < ntiles; t++) {
        if (t + 1 < ntiles) { load_tile(t + 1, (t + 1) & 1); CPC(); CPW1(); }
        else { CPW0(); }
        __syncthreads();

        const __half* A_ = As + (t & 1) * A_STh;
        const __half* B_ = Bs + (t & 1) * B_STh;
        #pragma unroll
        for (int kc = 0; kc < 4; kc++) {
            uint32_t a[2][4], b[8][2];
            #pragma unroll
            for (int mt = 0; mt < 2; mt++)
                ldsm4(a[mt], su32(&A_[(wid*32 + mt*16 + lrow)*APh + kc*16 + lch]));
            #pragma unroll
            for (int ntp = 0; ntp < 4; ntp++) {
                uint32_t r4[4];
                ldsm4t(r4, su32(&B_[(kc*16 + (j8&1)*8 + i8)*BPh + ntp*16 + (j8>>1)*8]));
                b[2*ntp][0]   = r4[0]; b[2*ntp][1]   = r4[1];
                b[2*ntp+1][0] = r4[2]; b[2*ntp+1][1] = r4[3];
            }
            #pragma unroll
            for (int mt = 0; mt < 2; mt++)
                #pragma unroll
                for (int nt = 0; nt < 8; nt++)
                    mma16(acc[mt][nt], a[mt], b[nt]);
        }
        __syncthreads();
    }
}

// ---------------------------------------------------------------------------
// Kernel 1: fused QKV. grid=(ROWS/128, 36), block=128.
// ---------------------------------------------------------------------------
__global__ void __launch_bounds__(128, 4) qkv_kernel(
    const float* __restrict__ bq, const float* __restrict__ bk,
    const float* __restrict__ bv)
{
    extern __shared__ __half smh[];
    __half* As = smh;
    __half* Bs = smh + 2*A_STh;

    const int nb = blockIdx.y;
    const int sel = nb / 12;
    const int h = nb % 12;
    const __half* W   = (sel == 0) ? g_wqh : ((sel == 1) ? g_wkh : g_wvh);
    const float* bias = (sel == 0) ? bq : ((sel == 1) ? bk : bv);
    __half* out       = (sel == 0) ? g_q : ((sel == 1) ? g_k : g_v);
    const float osc   = (sel == 0) ? QSC : 1.0f;

    const int row0 = blockIdx.x * 128;

    float acc[2][8][4] = {};
    auto bsrc = [&](int k, int c8) {
        return W + ((size_t)h * DM + k) * DH + c8 * 8;
    };
    gemm128x64(g_xh + (size_t)row0 * DM, bsrc, DM/64, As, Bs, acc);

    const int tid = threadIdx.x, lane = tid & 31, wid = tid >> 5;
    const int lq = lane >> 2, lr = lane & 3;

    #pragma unroll
    for (int mt = 0; mt < 2; mt++) {
        #pragma unroll
        for (int nt = 0; nt < 8; nt++) {
            int d = nt*8 + 2*lr;
            float bz0 = bias[h*DH + d], bz1 = bias[h*DH + d + 1];
            #pragma unroll
            for (int half_ = 0; half_ < 2; half_++) {
                int gr = row0 + wid*32 + mt*16 + lq + half_*8;
                int bb = gr / SEQ, s = gr % SEQ;
                size_t base = (((size_t)bb*NH + h)*SEQ + s)*DH + d;
                *(__half2*)(out + base) = __floats2half2_rn(
                    (acc[mt][nt][half_*2+0] + bz0) * osc,
                    (acc[mt][nt][half_*2+1] + bz1) * osc);
            }
        }
    }
}

// ---------------------------------------------------------------------------
// Kernel 3: output projection. grid=(ROWS/128, 12), block=128. fp32 out.
// ---------------------------------------------------------------------------
__global__ void __launch_bounds__(128, 4) oproj_kernel(
    const float* __restrict__ bo, float* __restrict__ out)
{
    extern __shared__ __half smh[];
    __half* As = smh;
    __half* Bs = smh + 2*A_STh;

    const int row0 = blockIdx.x * 128;
    const int n0   = blockIdx.y * 64;

    float acc[2][8][4] = {};
    auto bsrc = [&](int k, int c8) {
        return g_woh + (size_t)k * DM + n0 + c8 * 8;
    };
    gemm128x64(g_zh + (size_t)row0 * DM, bsrc, DM/64, As, Bs, acc);

    const int tid = threadIdx.x, lane = tid & 31, wid = tid >> 5;
    const int lq = lane >> 2, lr = lane & 3;

    #pragma unroll
    for (int mt = 0; mt < 2; mt++) {
        #pragma unroll
        for (int nt = 0; nt < 8; nt++) {
            int c = n0 + nt*8 + 2*lr;
            float bz0 = bo[c], bz1 = bo[c + 1];
            #pragma unroll
            for (int half_ = 0; half_ < 2; half_++) {
                size_t orow = (size_t)(row0 + wid*32 + mt*16 + lq + half_*8) * DM;
                out[orow + c]     = acc[mt][nt][half_*2+0] + bz0;
                out[orow + c + 1] = acc[mt][nt][half_*2+1] + bz1;
            }
        }
    }
}

// ===========================================================================
// Kernel 2: causal flash attention, fp16, FA2 register-resident Q and P.
// NOW __launch_bounds__(128, 3): cap regs at 170 -> 3 blocks/SM (12 warps),
// smem 3 x 73.7KB = 221KB fits. Only change vs R13.
// ===========================================================================
#define QTILE 128
#define PHp 72
#define KVST (64*PHp)
#define STG (2*KVST)
#define KV_OFF (QTILE*PHp)
#define FLASH_SMEM ((QTILE*PHp + 3*STG) * 2)

__global__ void __launch_bounds__(128, 3) flash_kernel()
{
    extern __shared__ __half smh[];
    __half* Qs = smh;

    const int qt = (int)gridDim.x - 1 - (int)blockIdx.x;
    const int h  = blockIdx.y;
    const int b  = blockIdx.z;
    const int q0 = qt * QTILE;

    const size_t hb = ((size_t)b * NH + h) * SEQ * DH;
    const __half* qp = g_q + hb;
    const __half* kp = g_k + hb;
    const __half* vp = g_v + hb;

    const int tid  = threadIdx.x;
    const int lane = tid & 31;
    const int wid  = tid >> 5;
    const int lq   = lane >> 2, lr = lane & 3;
    const int lrow = lane & 15, lch = (lane >> 4) * 8;
    const int j8 = lane >> 3, i8 = lane & 7;
    const int wbase = wid * 32;

    auto loadKV = [&](int kt, int s) {
        int k0 = kt * 64;
        #pragma unroll
        for (int i = 0; i < 4; i++) {
            int id = tid + i * 128;
            int r = id >> 3, c8 = id & 7;
            CPA(su32(&smh[KV_OFF + s*STG + r*PHp + c8*8]),        kp + (size_t)(k0+r)*DH + c8*8);
            CPA(su32(&smh[KV_OFF + s*STG + KVST + r*PHp + c8*8]), vp + (size_t)(k0+r)*DH + c8*8);
        }
    };

    #pragma unroll
    for (int i = 0; i < 8; i++) {
        int id = tid + i * 128;
        int r = id >> 3, c8 = id & 7;
        CPA(su32(&Qs[r*PHp + c8*8]), qp + (size_t)(q0+r)*DH + c8*8);
    }
    loadKV(0, 0);
    CPC();
    const int nkt = 2*qt + 2;
    if (nkt > 1) loadKV(1, 1);
    CPC();

    CPW1();
    __syncthreads();

    uint32_t qa[2][4][4];
    #pragma unroll
    for (int mt = 0; mt < 2; mt++)
        #pragma unroll
        for (int kc = 0; kc < 4; kc++)
            ldsm4(qa[mt][kc], su32(&Qs[(wbase + mt*16 + lrow)*PHp + kc*16 + lch]));

    float o[2][8][4] = {};
    float mrow[2][2], lrow2[2][2];
    #pragma unroll
    for (int mt = 0; mt < 2; mt++) { mrow[mt][0]=-INFINITY; mrow[mt][1]=-INFINITY; lrow2[mt][0]=0.f; lrow2[mt][1]=0.f; }

    for (int kt = 0; kt < nkt; kt++) {
        if (kt > 0) {
            if (kt + 1 < nkt) { CPW1(); } else { CPW0(); }
            __syncthreads();
        }
        if (kt + 2 < nkt) { loadKV(kt + 2, (kt + 2) % 3); CPC(); }

        const int k0 = kt * 64;
        const __half* K_ = smh + KV_OFF + (kt % 3) * STG;
        const __half* V_ = K_ + KVST;

        float sf[2][8][4] = {};
        #pragma unroll
        for (int kc = 0; kc < 4; kc++) {
            uint32_t bk2[8][2];
            #pragma unroll
            for (int ntp = 0; ntp < 4; ntp++) {
                uint32_t r4[4];
                ldsm4(r4, su32(&K_[(ntp*16 + (j8>>1)*8 + i8)*PHp + kc*16 + (j8&1)*8]));
                bk2[2*ntp][0]   = r4[0]; bk2[2*ntp][1]   = r4[1];
                bk2[2*ntp+1][0] = r4[2]; bk2[2*ntp+1][1] = r4[3];
            }
            #pragma unroll
            for (int nt = 0; nt < 8; nt++) {
                mma16(sf[0][nt], qa[0][kc], bk2[nt]);
                mma16(sf[1][nt], qa[1][kc], bk2[nt]);
            }
        }

        const bool nm = (k0 + 63 > q0 + wbase);
        if (nm) {
            #pragma unroll
            for (int mt = 0; mt < 2; mt++) {
                int grow0 = q0 + wbase + mt*16 + lq;
                #pragma unroll
                for (int nt = 0; nt < 8; nt++) {
                    #pragma unroll
                    for (int e = 0; e < 4; e++) {
                        int gc = k0 + nt*8 + 2*lr + (e & 1);
                        int grow = grow0 + ((e >= 2) ? 8 : 0);
                        if (gc > grow) sf[mt][nt][e] = -1e30f;
                    }
                }
            }
        }

        uint32_t plo[2][8], phi[2][8];
        #pragma unroll
        for (int mt = 0; mt < 2; mt++) {
            float t0 = -INFINITY, t1 = -INFINITY;
            #pragma unroll
            for (int nt = 0; nt < 8; nt++) {
                t0 = fmaxf(t0, fmaxf(sf[mt][nt][0], sf[mt][nt][1]));
                t1 = fmaxf(t1, fmaxf(sf[mt][nt][2], sf[mt][nt][3]));
            }
            t0 = fmaxf(t0, __shfl_xor_sync(0xffffffffu, t0, 1));
            t0 = fmaxf(t0, __shfl_xor_sync(0xffffffffu, t0, 2));
            t1 = fmaxf(t1, __shfl_xor_sync(0xffffffffu, t1, 1));
            t1 = fmaxf(t1, __shfl_xor_sync(0xffffffffu, t1, 2));

            float mn0 = fmaxf(mrow[mt][0], t0), mn1 = fmaxf(mrow[mt][1], t1);
            float sc0 = ex2f(mrow[mt][0] - mn0), sc1 = ex2f(mrow[mt][1] - mn1);
            mrow[mt][0] = mn0; mrow[mt][1] = mn1;

            float s0 = 0.f, s1 = 0.f;
            #pragma unroll
            for (int nt = 0; nt < 8; nt++) {
                float p0 = ex2f(sf[mt][nt][0] - mn0);
                float p1 = ex2f(sf[mt][nt][1] - mn0);
                float p2 = ex2f(sf[mt][nt][2] - mn1);
                float p3 = ex2f(sf[mt][nt][3] - mn1);
                s0 += p0 + p1; s1 += p2 + p3;
                plo[mt][nt] = h2u(__floats2half2_rn(p0, p1));
                phi[mt][nt] = h2u(__floats2half2_rn(p2, p3));
            }
            s0 += __shfl_xor_sync(0xffffffffu, s0, 1);
            s0 += __shfl_xor_sync(0xffffffffu, s0, 2);
            s1 += __shfl_xor_sync(0xffffffffu, s1, 1);
            s1 += __shfl_xor_sync(0xffffffffu, s1, 2);
            lrow2[mt][0] = lrow2[mt][0] * sc0 + s0;
            lrow2[mt][1] = lrow2[mt][1] * sc1 + s1;

            #pragma unroll
            for (int nt = 0; nt < 8; nt++) {
                o[mt][nt][0] *= sc0; o[mt][nt][1] *= sc0;
                o[mt][nt][2] *= sc1; o[mt][nt][3] *= sc1;
            }
        }

        #pragma unroll
        for (int kc = 0; kc < 4; kc++) {
            uint32_t bv2[8][2];
            #pragma unroll
            for (int dp = 0; dp < 4; dp++) {
                uint32_t r4[4];
                ldsm4t(r4, su32(&V_[(kc*16 + (j8&1)*8 + i8)*PHp + dp*16 + (j8>>1)*8]));
                bv2[2*dp][0]   = r4[0]; bv2[2*dp][1]   = r4[1];
                bv2[2*dp+1][0] = r4[2]; bv2[2*dp+1][1] = r4[3];
            }
            #pragma unroll
            for (int mt = 0; mt < 2; mt++) {
                uint32_t a[4] = { plo[mt][2*kc], phi[mt][2*kc],
                                  plo[mt][2*kc+1], phi[mt][2*kc+1] };
                #pragma unroll
                for (int nt = 0; nt < 8; nt++)
                    mma16(o[mt][nt], a, bv2[nt]);
            }
        }
    }

    #pragma unroll
    for (int mt = 0; mt < 2; mt++) {
        float inv0 = 1.f / lrow2[mt][0], inv1 = 1.f / lrow2[mt][1];
        size_t r0 = (size_t)b * SEQ + q0 + wbase + mt*16 + lq;
        #pragma unroll
        for (int nt = 0; nt < 8; nt++) {
            int col = h*DH + nt*8 + 2*lr;
            *(__half2*)&g_zh[r0 * DM + col] =
                __floats2half2_rn(o[mt][nt][0] * inv0, o[mt][nt][1] * inv0);
            *(__half2*)&g_zh[(r0 + 8) * DM + col] =
                __floats2half2_rn(o[mt][nt][2] * inv1, o[mt][nt][3] * inv1);
        }
    }
}

extern "C" void kernel_launch(void* const* d_in, const int* in_sizes, int n_in,
                              void* d_out, int out_size)
{
    const float* x  = (const float*)d_in[0];
    const float* Wq = (const float*)d_in[1];
    const float* Wk = (const float*)d_in[2];
    const float* Wv = (const float*)d_in[3];
    const float* Wo = (const float*)d_in[4];
    const float* bq = (const float*)d_in[5];
    const float* bk = (const float*)d_in[6];
    const float* bv = (const float*)d_in[7];
    const float* bo = (const float*)d_in[8];
    float* out = (float*)d_out;

    cudaFuncSetAttribute(qkv_kernel,   cudaFuncAttributeMaxDynamicSharedMemorySize, GEMM_SMEM);
    cudaFuncSetAttribute(oproj_kernel, cudaFuncAttributeMaxDynamicSharedMemorySize, GEMM_SMEM);
    cudaFuncSetAttribute(flash_kernel, cudaFuncAttributeMaxDynamicSharedMemorySize, FLASH_SMEM);

    cvt_all_kernel<<<(CVT_TOTAL + 255)/256, 256>>>(
        (const float4*)x, (const float4*)Wq, (const float4*)Wk,
        (const float4*)Wv, (const float4*)Wo);

    qkv_kernel<<<dim3(ROWS/128, 36), 128, GEMM_SMEM>>>(bq, bk, bv);
    flash_kernel<<<dim3(SEQ/QTILE, NH, BATCH), 128, FLASH_SMEM>>>();
    oproj_kernel<<<dim3(ROWS/128, 12), 128, GEMM_SMEM>>>(bo, out);
}

// round 15
// speedup vs baseline: 1.0846x; 1.0846x over previous
#include <cuda_runtime.h>
#include <cuda_fp16.h>
#include <math.h>
#include <stdint.h>
#include <string.h>

#define BATCH 4
#define SEQ 2048
#define DM 768
#define NH 12
#define DH 64
#define ROWS (BATCH*SEQ)

__device__ __half g_xh [(size_t)ROWS*DM];
__device__ __half g_wqh[(size_t)NH*DM*DH];
__device__ __half g_wkh[(size_t)NH*DM*DH];
__device__ __half g_wvh[(size_t)NH*DM*DH];
__device__ __half g_woh[(size_t)DM*DM];
__device__ __half g_q[(size_t)BATCH*NH*SEQ*DH];  // pre-scaled by 0.125*log2e
__device__ __half g_k[(size_t)BATCH*NH*SEQ*DH];
__device__ __half g_v[(size_t)BATCH*NH*SEQ*DH];
__device__ __half g_zh[(size_t)ROWS*DM];

#define QSC 0.1803368801111154f  /* 0.125 * log2(e) */

__device__ __forceinline__ float ex2f(float x) {
    float y; asm("ex2.approx.f32 %0, %1;" : "=f"(y) : "f"(x)); return y;
}
__device__ __forceinline__ uint32_t h2u(__half2 h) {
    uint32_t u;
    memcpy(&u, &h, 4);
    return u;
}
__device__ __forceinline__ void mma16(float* d, const uint32_t* a, const uint32_t* b) {
    asm volatile(
        "mma.sync.aligned.m16n8k16.row.col.f32.f16.f16.f32 "
        "{%0,%1,%2,%3}, {%4,%5,%6,%7}, {%8,%9}, {%0,%1,%2,%3};\n"
        : "+f"(d[0]), "+f"(d[1]), "+f"(d[2]), "+f"(d[3])
        : "r"(a[0]), "r"(a[1]), "r"(a[2]), "r"(a[3]), "r"(b[0]), "r"(b[1]));
}
__device__ __forceinline__ void ldsm4(uint32_t* r, uint32_t addr) {
    asm volatile("ldmatrix.sync.aligned.m8n8.x4.shared.b16 {%0,%1,%2,%3}, [%4];"
        : "=r"(r[0]), "=r"(r[1]), "=r"(r[2]), "=r"(r[3]) : "r"(addr));
}
__device__ __forceinline__ void ldsm4t(uint32_t* r, uint32_t addr) {
    asm volatile("ldmatrix.sync.aligned.m8n8.x4.trans.shared.b16 {%0,%1,%2,%3}, [%4];"
        : "=r"(r[0]), "=r"(r[1]), "=r"(r[2]), "=r"(r[3]) : "r"(addr));
}
__device__ __forceinline__ uint32_t su32(const void* p) {
    return (uint32_t)__cvta_generic_to_shared(p);
}
#define CPA(dst, src) asm volatile("cp.async.cg.shared.global [%0], [%1], 16;" :: "r"(dst), "l"(src))
#define CPC() asm volatile("cp.async.commit_group;")
#define CPW1() asm volatile("cp.async.wait_group 1;")
#define CPW0() asm volatile("cp.async.wait_group 0;")

// ---------------------------------------------------------------------------
// Prep: single fused fp32 -> fp16 conversion
// ---------------------------------------------------------------------------
#define NX4 (ROWS*DM/4)
#define NW4 (NH*DM*DH/4)
__global__ void __launch_bounds__(256) cvt_all_kernel(
    const float4* __restrict__ x,  const float4* __restrict__ wq,
    const float4* __restrict__ wk, const float4* __restrict__ wv,
    const float4* __restrict__ wo)
{
    int i = blockIdx.x * 256 + threadIdx.x;
    const float4* in;
    __half2* out;
    int j;
    if (i < NX4)                { in = x;  out = (__half2*)g_xh;  j = i; }
    else if (i < NX4 + NW4)     { in = wq; out = (__half2*)g_wqh; j = i - NX4; }
    else if (i < NX4 + 2*NW4)   { in = wk; out = (__half2*)g_wkh; j = i - NX4 - NW4; }
    else if (i < NX4 + 3*NW4)   { in = wv; out = (__half2*)g_wvh; j = i - NX4 - 2*NW4; }
    else if (i < NX4 + 4*NW4)   { in = wo; out = (__half2*)g_woh; j = i - NX4 - 3*NW4; }
    else return;
    float4 v = in[j];
    out[2*j]   = __floats2half2_rn(v.x, v.y);
    out[2*j+1] = __floats2half2_rn(v.z, v.w);
}
#define CVT_TOTAL (NX4 + 4*NW4)

// ===========================================================================
// GEMM: C[128x64], 128 threads (4 warps, 32x64 each), BK=64, 2-stage
// cp.async. smem 55.3KB -> 4 blocks/SM. (Unchanged from R13.)
// ===========================================================================
#define APh 72
#define BPh 72
#define A_STh (128*APh)
#define B_STh (64*BPh)
#define GEMM_SMEM ((2*A_STh + 2*B_STh) * 2)

template <typename FB>
__device__ __forceinline__ void gemm128x64(const __half* __restrict__ Ag,
                                           FB bsrc, int ntiles,
                                           __half* As, __half* Bs, float acc[2][8][4])
{
    const int tid = threadIdx.x;
    const int lane = tid & 31, wid = tid >> 5;
    const int lrow = lane & 15, lch = (lane >> 4) * 8;
    const int j8 = lane >> 3, i8 = lane & 7;

    auto load_tile = [&](int t, int s) {
        #pragma unroll
        for (int i = 0; i < 8; i++) {
            int id = tid + i * 128;
            int r = id >> 3, c8 = id & 7;
            CPA(su32(&As[s*A_STh + r*APh + c8*8]), Ag + (size_t)r * DM + t*64 + c8*8);
        }
        #pragma unroll
        for (int i = 0; i < 4; i++) {
            int id = tid + i * 128;
            int kr = id >> 3, c8 = id & 7;
            CPA(su32(&Bs[s*B_STh + kr*BPh + c8*8]), bsrc(t*64 + kr, c8));
        }
    };

    load_tile(0, 0); CPC();

    for (int t = 0; t < ntiles; t++) {
        if (t + 1 < ntiles) { load_tile(t + 1, (t + 1) & 1); CPC(); CPW1(); }
        else { CPW0(); }
        __syncthreads();

        const __half* A_ = As + (t & 1) * A_STh;
        const __half* B_ = Bs + (t & 1) * B_STh;
        #pragma unroll
        for (int kc = 0; kc < 4; kc++) {
            uint32_t a[2][4], b[8][2];
            #pragma unroll
            for (int mt = 0; mt < 2; mt++)
                ldsm4(a[mt], su32(&A_[(wid*32 + mt*16 + lrow)*APh + kc*16 + lch]));
            #pragma unroll
            for (int ntp = 0; ntp < 4; ntp++) {
                uint32_t r4[4];
                ldsm4t(r4, su32(&B_[(kc*16 + (j8&1)*8 + i8)*BPh + ntp*16 + (j8>>1)*8]));
                b[2*ntp][0]   = r4[0]; b[2*ntp][1]   = r4[1];
                b[2*ntp+1][0] = r4[2]; b[2*ntp+1][1] = r4[3];
            }
            #pragma unroll
            for (int mt = 0; mt < 2; mt++)
                #pragma unroll
                for (int nt = 0; nt < 8; nt++)
                    mma16(acc[mt][nt], a[mt], b[nt]);
        }
        __syncthreads();
    }
}

// ---------------------------------------------------------------------------
// Kernel 1: fused QKV. grid=(ROWS/128, 36), block=128.
// ---------------------------------------------------------------------------
__global__ void __launch_bounds__(128, 4) qkv_kernel(
    const float* __restrict__ bq, const float* __restrict__ bk,
    const float* __restrict__ bv)
{
    extern __shared__ __half smh[];
    __half* As = smh;
    __half* Bs = smh + 2*A_STh;

    const int nb = blockIdx.y;
    const int sel = nb / 12;
    const int h = nb % 12;
    const __half* W   = (sel == 0) ? g_wqh : ((sel == 1) ? g_wkh : g_wvh);
    const float* bias = (sel == 0) ? bq : ((sel == 1) ? bk : bv);
    __half* out       = (sel == 0) ? g_q : ((sel == 1) ? g_k : g_v);
    const float osc   = (sel == 0) ? QSC : 1.0f;

    const int row0 = blockIdx.x * 128;

    float acc[2][8][4] = {};
    auto bsrc = [&](int k, int c8) {
        return W + ((size_t)h * DM + k) * DH + c8 * 8;
    };
    gemm128x64(g_xh + (size_t)row0 * DM, bsrc, DM/64, As, Bs, acc);

    const int tid = threadIdx.x, lane = tid & 31, wid = tid >> 5;
    const int lq = lane >> 2, lr = lane & 3;

    #pragma unroll
    for (int mt = 0; mt < 2; mt++) {
        #pragma unroll
        for (int nt = 0; nt < 8; nt++) {
            int d = nt*8 + 2*lr;
            float bz0 = bias[h*DH + d], bz1 = bias[h*DH + d + 1];
            #pragma unroll
            for (int half_ = 0; half_ < 2; half_++) {
                int gr = row0 + wid*32 + mt*16 + lq + half_*8;
                int bb = gr / SEQ, s = gr % SEQ;
                size_t base = (((size_t)bb*NH + h)*SEQ + s)*DH + d;
                *(__half2*)(out + base) = __floats2half2_rn(
                    (acc[mt][nt][half_*2+0] + bz0) * osc,
                    (acc[mt][nt][half_*2+1] + bz1) * osc);
            }
        }
    }
}

// ---------------------------------------------------------------------------
// Kernel 3: output projection. grid=(ROWS/128, 12), block=128. fp32 out.
// ---------------------------------------------------------------------------
__global__ void __launch_bounds__(128, 4) oproj_kernel(
    const float* __restrict__ bo, float* __restrict__ out)
{
    extern __shared__ __half smh[];
    __half* As = smh;
    __half* Bs = smh + 2*A_STh;

    const int row0 = blockIdx.x * 128;
    const int n0   = blockIdx.y * 64;

    float acc[2][8][4] = {};
    auto bsrc = [&](int k, int c8) {
        return g_woh + (size_t)k * DM + n0 + c8 * 8;
    };
    gemm128x64(g_zh + (size_t)row0 * DM, bsrc, DM/64, As, Bs, acc);

    const int tid = threadIdx.x, lane = tid & 31, wid = tid >> 5;
    const int lq = lane >> 2, lr = lane & 3;

    #pragma unroll
    for (int mt = 0; mt < 2; mt++) {
        #pragma unroll
        for (int nt = 0; nt < 8; nt++) {
            int c = n0 + nt*8 + 2*lr;
            float bz0 = bo[c], bz1 = bo[c + 1];
            #pragma unroll
            for (int half_ = 0; half_ < 2; half_++) {
                size_t orow = (size_t)(row0 + wid*32 + mt*16 + lq + half_*8) * DM;
                out[orow + c]     = acc[mt][nt][half_*2+0] + bz0;
                out[orow + c + 1] = acc[mt][nt][half_*2+1] + bz1;
            }
        }
    }
}

// ===========================================================================
// Kernel 2: causal flash attention, fp16, register-resident P.
// Q frags reloaded from smem per k-tile (saves 32 regs) so that
// __launch_bounds__(128,3) caps regs ~170 WITHOUT spilling -> 3 blocks/SM.
// ===========================================================================
#define QTILE 128
#define PHp 72
#define KVST (64*PHp)
#define STG (2*KVST)
#define KV_OFF (QTILE*PHp)
#define FLASH_SMEM ((QTILE*PHp + 3*STG) * 2)

__global__ void __launch_bounds__(128, 3) flash_kernel()
{
    extern __shared__ __half smh[];
    __half* Qs = smh;

    const int qt = (int)gridDim.x - 1 - (int)blockIdx.x;
    const int h  = blockIdx.y;
    const int b  = blockIdx.z;
    const int q0 = qt * QTILE;

    const size_t hb = ((size_t)b * NH + h) * SEQ * DH;
    const __half* qp = g_q + hb;
    const __half* kp = g_k + hb;
    const __half* vp = g_v + hb;

    const int tid  = threadIdx.x;
    const int lane = tid & 31;
    const int wid  = tid >> 5;
    const int lq   = lane >> 2, lr = lane & 3;
    const int lrow = lane & 15, lch = (lane >> 4) * 8;
    const int j8 = lane >> 3, i8 = lane & 7;
    const int wbase = wid * 32;

    auto loadKV = [&](int kt, int s) {
        int k0 = kt * 64;
        #pragma unroll
        for (int i = 0; i < 4; i++) {
            int id = tid + i * 128;
            int r = id >> 3, c8 = id & 7;
            CPA(su32(&smh[KV_OFF + s*STG + r*PHp + c8*8]),        kp + (size_t)(k0+r)*DH + c8*8);
            CPA(su32(&smh[KV_OFF + s*STG + KVST + r*PHp + c8*8]), vp + (size_t)(k0+r)*DH + c8*8);
        }
    };

    #pragma unroll
    for (int i = 0; i < 8; i++) {
        int id = tid + i * 128;
        int r = id >> 3, c8 = id & 7;
        CPA(su32(&Qs[r*PHp + c8*8]), qp + (size_t)(q0+r)*DH + c8*8);
    }
    loadKV(0, 0);
    CPC();
    const int nkt = 2*qt + 2;
    if (nkt > 1) loadKV(1, 1);
    CPC();

    CPW1();
    __syncthreads();

    float o[2][8][4] = {};
    float mrow[2][2], lrow2[2][2];
    #pragma unroll
    for (int mt = 0; mt < 2; mt++) { mrow[mt][0]=-INFINITY; mrow[mt][1]=-INFINITY; lrow2[mt][0]=0.f; lrow2[mt][1]=0.f; }

    for (int kt = 0; kt < nkt; kt++) {
        if (kt > 0) {
            if (kt + 1 < nkt) { CPW1(); } else { CPW0(); }
            __syncthreads();
        }
        if (kt + 2 < nkt) { loadKV(kt + 2, (kt + 2) % 3); CPC(); }

        const int k0 = kt * 64;
        const __half* K_ = smh + KV_OFF + (kt % 3) * STG;
        const __half* V_ = K_ + KVST;

        // S = Q @ K^T (log2 domain); Q frags loaded from smem per kc
        float sf[2][8][4] = {};
        #pragma unroll
        for (int kc = 0; kc < 4; kc++) {
            uint32_t qa[2][4], bk2[8][2];
            #pragma unroll
            for (int mt = 0; mt < 2; mt++)
                ldsm4(qa[mt], su32(&Qs[(wbase + mt*16 + lrow)*PHp + kc*16 + lch]));
            #pragma unroll
            for (int ntp = 0; ntp < 4; ntp++) {
                uint32_t r4[4];
                ldsm4(r4, su32(&K_[(ntp*16 + (j8>>1)*8 + i8)*PHp + kc*16 + (j8&1)*8]));
                bk2[2*ntp][0]   = r4[0]; bk2[2*ntp][1]   = r4[1];
                bk2[2*ntp+1][0] = r4[2]; bk2[2*ntp+1][1] = r4[3];
            }
            #pragma unroll
            for (int nt = 0; nt < 8; nt++) {
                mma16(sf[0][nt], qa[0], bk2[nt]);
                mma16(sf[1][nt], qa[1], bk2[nt]);
            }
        }

        const bool nm = (k0 + 63 > q0 + wbase);
        if (nm) {
            #pragma unroll
            for (int mt = 0; mt < 2; mt++) {
                int grow0 = q0 + wbase + mt*16 + lq;
                #pragma unroll
                for (int nt = 0; nt < 8; nt++) {
                    #pragma unroll
                    for (int e = 0; e < 4; e++) {
                        int gc = k0 + nt*8 + 2*lr + (e & 1);
                        int grow = grow0 + ((e >= 2) ? 8 : 0);
                        if (gc > grow) sf[mt][nt][e] = -1e30f;
                    }
                }
            }
        }

        uint32_t plo[2][8], phi[2][8];
        #pragma unroll
        for (int mt = 0; mt < 2; mt++) {
            float t0 = -INFINITY, t1 = -INFINITY;
            #pragma unroll
            for (int nt = 0; nt < 8; nt++) {
                t0 = fmaxf(t0, fmaxf(sf[mt][nt][0], sf[mt][nt][1]));
                t1 = fmaxf(t1, fmaxf(sf[mt][nt][2], sf[mt][nt][3]));
            }
            t0 = fmaxf(t0, __shfl_xor_sync(0xffffffffu, t0, 1));
            t0 = fmaxf(t0, __shfl_xor_sync(0xffffffffu, t0, 2));
            t1 = fmaxf(t1, __shfl_xor_sync(0xffffffffu, t1, 1));
            t1 = fmaxf(t1, __shfl_xor_sync(0xffffffffu, t1, 2));

            float mn0 = fmaxf(mrow[mt][0], t0), mn1 = fmaxf(mrow[mt][1], t1);
            float sc0 = ex2f(mrow[mt][0] - mn0), sc1 = ex2f(mrow[mt][1] - mn1);
            mrow[mt][0] = mn0; mrow[mt][1] = mn1;

            float s0 = 0.f, s1 = 0.f;
            #pragma unroll
            for (int nt = 0; nt < 8; nt++) {
                float p0 = ex2f(sf[mt][nt][0] - mn0);
                float p1 = ex2f(sf[mt][nt][1] - mn0);
                float p2 = ex2f(sf[mt][nt][2] - mn1);
                float p3 = ex2f(sf[mt][nt][3] - mn1);
                s0 += p0 + p1; s1 += p2 + p3;
                plo[mt][nt] = h2u(__floats2half2_rn(p0, p1));
                phi[mt][nt] = h2u(__floats2half2_rn(p2, p3));
            }
            s0 += __shfl_xor_sync(0xffffffffu, s0, 1);
            s0 += __shfl_xor_sync(0xffffffffu, s0, 2);
            s1 += __shfl_xor_sync(0xffffffffu, s1, 1);
            s1 += __shfl_xor_sync(0xffffffffu, s1, 2);
            lrow2[mt][0] = lrow2[mt][0] * sc0 + s0;
            lrow2[mt][1] = lrow2[mt][1] * sc1 + s1;

            #pragma unroll
            for (int nt = 0; nt < 8; nt++) {
                o[mt][nt][0] *= sc0; o[mt][nt][1] *= sc0;
                o[mt][nt][2] *= sc1; o[mt][nt][3] *= sc1;
            }
        }

        #pragma unroll
        for (int kc = 0; kc < 4; kc++) {
            uint32_t bv2[8][2];
            #pragma unroll
            for (int dp = 0; dp < 4; dp++) {
                uint32_t r4[4];
                ldsm4t(r4, su32(&V_[(kc*16 + (j8&1)*8 + i8)*PHp + dp*16 + (j8>>1)*8]));
                bv2[2*dp][0]   = r4[0]; bv2[2*dp][1]   = r4[1];
                bv2[2*dp+1][0] = r4[2]; bv2[2*dp+1][1] = r4[3];
            }
            #pragma unroll
            for (int mt = 0; mt < 2; mt++) {
                uint32_t a[4] = { plo[mt][2*kc], phi[mt][2*kc],
                                  plo[mt][2*kc+1], phi[mt][2*kc+1] };
                #pragma unroll
                for (int nt = 0; nt < 8; nt++)
                    mma16(o[mt][nt], a, bv2[nt]);
            }
        }
    }

    #pragma unroll
    for (int mt = 0; mt < 2; mt++) {
        float inv0 = 1.f / lrow2[mt][0], inv1 = 1.f / lrow2[mt][1];
        size_t r0 = (size_t)b * SEQ + q0 + wbase + mt*16 + lq;
        #pragma unroll
        for (int nt = 0; nt < 8; nt++) {
            int col = h*DH + nt*8 + 2*lr;
            *(__half2*)&g_zh[r0 * DM + col] =
                __floats2half2_rn(o[mt][nt][0] * inv0, o[mt][nt][1] * inv0);
            *(__half2*)&g_zh[(r0 + 8) * DM + col] =
                __floats2half2_rn(o[mt][nt][2] * inv1, o[mt][nt][3] * inv1);
        }
    }
}

extern "C" void kernel_launch(void* const* d_in, const int* in_sizes, int n_in,
                              void* d_out, int out_size)
{
    const float* x  = (const float*)d_in[0];
    const float* Wq = (const float*)d_in[1];
    const float* Wk = (const float*)d_in[2];
    const float* Wv = (const float*)d_in[3];
    const float* Wo = (const float*)d_in[4];
    const float* bq = (const float*)d_in[5];
    const float* bk = (const float*)d_in[6];
    const float* bv = (const float*)d_in[7];
    const float* bo = (const float*)d_in[8];
    float* out = (float*)d_out;

    cudaFuncSetAttribute(qkv_kernel,   cudaFuncAttributeMaxDynamicSharedMemorySize, GEMM_SMEM);
    cudaFuncSetAttribute(oproj_kernel, cudaFuncAttributeMaxDynamicSharedMemorySize, GEMM_SMEM);
    cudaFuncSetAttribute(flash_kernel, cudaFuncAttributeMaxDynamicSharedMemorySize, FLASH_SMEM);

    cvt_all_kernel<<<(CVT_TOTAL + 255)/256, 256>>>(
        (const float4*)x, (const float4*)Wq, (const float4*)Wk,
        (const float4*)Wv, (const float4*)Wo);

    qkv_kernel<<<dim3(ROWS/128, 36), 128, GEMM_SMEM>>>(bq, bk, bv);
    flash_kernel<<<dim3(SEQ/QTILE, NH, BATCH), 128, FLASH_SMEM>>>();
    oproj_kernel<<<dim3(ROWS/128, 12), 128, GEMM_SMEM>>>(bo, out);
}

// round 16
// speedup vs baseline: 1.1114x; 1.0247x over previous
#include <cuda_runtime.h>
#include <cuda_fp16.h>
#include <math.h>
#include <stdint.h>
#include <string.h>

#define BATCH 4
#define SEQ 2048
#define DM 768
#define NH 12
#define DH 64
#define ROWS (BATCH*SEQ)

__device__ __half g_xh [(size_t)ROWS*DM];
__device__ __half g_wqh[(size_t)NH*DM*DH];
__device__ __half g_wkh[(size_t)NH*DM*DH];
__device__ __half g_wvh[(size_t)NH*DM*DH];
__device__ __half g_woh[(size_t)DM*DM];
__device__ __half g_q[(size_t)BATCH*NH*SEQ*DH];  // pre-scaled by 0.125*log2e
__device__ __half g_k[(size_t)BATCH*NH*SEQ*DH];
__device__ __half g_v[(size_t)BATCH*NH*SEQ*DH];
__device__ __half g_zh[(size_t)ROWS*DM];

#define QSC 0.1803368801111154f  /* 0.125 * log2(e) */

__device__ __forceinline__ float ex2f(float x) {
    float y; asm("ex2.approx.f32 %0, %1;" : "=f"(y) : "f"(x)); return y;
}
__device__ __forceinline__ uint32_t h2u(__half2 h) {
    uint32_t u;
    memcpy(&u, &h, 4);
    return u;
}
__device__ __forceinline__ void mma16(float* d, const uint32_t* a, const uint32_t* b) {
    asm volatile(
        "mma.sync.aligned.m16n8k16.row.col.f32.f16.f16.f32 "
        "{%0,%1,%2,%3}, {%4,%5,%6,%7}, {%8,%9}, {%0,%1,%2,%3};\n"
        : "+f"(d[0]), "+f"(d[1]), "+f"(d[2]), "+f"(d[3])
        : "r"(a[0]), "r"(a[1]), "r"(a[2]), "r"(a[3]), "r"(b[0]), "r"(b[1]));
}
__device__ __forceinline__ void ldsm4(uint32_t* r, uint32_t addr) {
    asm volatile("ldmatrix.sync.aligned.m8n8.x4.shared.b16 {%0,%1,%2,%3}, [%4];"
        : "=r"(r[0]), "=r"(r[1]), "=r"(r[2]), "=r"(r[3]) : "r"(addr));
}
__device__ __forceinline__ void ldsm4t(uint32_t* r, uint32_t addr) {
    asm volatile("ldmatrix.sync.aligned.m8n8.x4.trans.shared.b16 {%0,%1,%2,%3}, [%4];"
        : "=r"(r[0]), "=r"(r[1]), "=r"(r[2]), "=r"(r[3]) : "r"(addr));
}
__device__ __forceinline__ uint32_t su32(const void* p) {
    return (uint32_t)__cvta_generic_to_shared(p);
}
#define CPA(dst, src) asm volatile("cp.async.cg.shared.global [%0], [%1], 16;" :: "r"(dst), "l"(src))
#define CPC() asm volatile("cp.async.commit_group;")
#define CPW1() asm volatile("cp.async.wait_group 1;")
#define CPW0() asm volatile("cp.async.wait_group 0;")

// ---------------------------------------------------------------------------
// Prep: single fused fp32 -> fp16 conversion
// ---------------------------------------------------------------------------
#define NX4 (ROWS*DM/4)
#define NW4 (NH*DM*DH/4)
__global__ void __launch_bounds__(256) cvt_all_kernel(
    const float4* __restrict__ x,  const float4* __restrict__ wq,
    const float4* __restrict__ wk, const float4* __restrict__ wv,
    const float4* __restrict__ wo)
{
    int i = blockIdx.x * 256 + threadIdx.x;
    const float4* in;
    __half2* out;
    int j;
    if (i < NX4)                { in = x;  out = (__half2*)g_xh;  j = i; }
    else if (i < NX4 + NW4)     { in = wq; out = (__half2*)g_wqh; j = i - NX4; }
    else if (i < NX4 + 2*NW4)   { in = wk; out = (__half2*)g_wkh; j = i - NX4 - NW4; }
    else if (i < NX4 + 3*NW4)   { in = wv; out = (__half2*)g_wvh; j = i - NX4 - 2*NW4; }
    else if (i < NX4 + 4*NW4)   { in = wo; out = (__half2*)g_woh; j = i - NX4 - 3*NW4; }
    else return;
    float4 v = in[j];
    out[2*j]   = __floats2half2_rn(v.x, v.y);
    out[2*j+1] = __floats2half2_rn(v.z, v.w);
}
#define CVT_TOTAL (NX4 + 4*NW4)

// ===========================================================================
// GEMM: C[128x64], 128 threads (4 warps, 32x64 each), BK=64, 2-stage
// cp.async, SINGLE __syncthreads per K-tile (load issued after sync).
// smem 55.3KB -> 4 blocks/SM.
// ===========================================================================
#define APh 72
#define BPh 72
#define A_STh (128*APh)
#define B_STh (64*BPh)
#define GEMM_SMEM ((2*A_STh + 2*B_STh) * 2)

template <typename FB>
__device__ __forceinline__ void gemm128x64(const __half* __restrict__ Ag,
                                           FB bsrc, int ntiles,
                                           __half* As, __half* Bs, float acc[2][8][4])
{
    const int tid = threadIdx.x;
    const int lane = tid & 31, wid = tid >> 5;
    const int lrow = lane & 15, lch = (lane >> 4) * 8;
    const int j8 = lane >> 3, i8 = lane & 7;

    auto load_tile = [&](int t, int s) {
        #pragma unroll
        for (int i = 0; i < 8; i++) {
            int id = tid + i * 128;
            int r = id >> 3, c8 = id & 7;
            CPA(su32(&As[s*A_STh + r*APh + c8*8]), Ag + (size_t)r * DM + t*64 + c8*8);
        }
        #pragma unroll
        for (int i = 0; i < 4; i++) {
            int id = tid + i * 128;
            int kr = id >> 3, c8 = id & 7;
            CPA(su32(&Bs[s*B_STh + kr*BPh + c8*8]), bsrc(t*64 + kr, c8));
        }
    };

    load_tile(0, 0); CPC();

    for (int t = 0; t < ntiles; t++) {
        CPW0();              // wait load(t); it overlapped compute(t-1)
        __syncthreads();     // all warps done reading stage (t+1)&1 (tile t-1)
        if (t + 1 < ntiles) { load_tile(t + 1, (t + 1) & 1); CPC(); }

        const __half* A_ = As + (t & 1) * A_STh;
        const __half* B_ = Bs + (t & 1) * B_STh;
        #pragma unroll
        for (int kc = 0; kc < 4; kc++) {
            uint32_t a[2][4], b[8][2];
            #pragma unroll
            for (int mt = 0; mt < 2; mt++)
                ldsm4(a[mt], su32(&A_[(wid*32 + mt*16 + lrow)*APh + kc*16 + lch]));
            #pragma unroll
            for (int ntp = 0; ntp < 4; ntp++) {
                uint32_t r4[4];
                ldsm4t(r4, su32(&B_[(kc*16 + (j8&1)*8 + i8)*BPh + ntp*16 + (j8>>1)*8]));
                b[2*ntp][0]   = r4[0]; b[2*ntp][1]   = r4[1];
                b[2*ntp+1][0] = r4[2]; b[2*ntp+1][1] = r4[3];
            }
            #pragma unroll
            for (int mt = 0; mt < 2; mt++)
                #pragma unroll
                for (int nt = 0; nt < 8; nt++)
                    mma16(acc[mt][nt], a[mt], b[nt]);
        }
    }
}

// ---------------------------------------------------------------------------
// Kernel 1: fused QKV. grid=(ROWS/128, 36), block=128.
// ---------------------------------------------------------------------------
__global__ void __launch_bounds__(128, 4) qkv_kernel(
    const float* __restrict__ bq, const float* __restrict__ bk,
    const float* __restrict__ bv)
{
    extern __shared__ __half smh[];
    __half* As = smh;
    __half* Bs = smh + 2*A_STh;

    const int nb = blockIdx.y;
    const int sel = nb / 12;
    const int h = nb % 12;
    const __half* W   = (sel == 0) ? g_wqh : ((sel == 1) ? g_wkh : g_wvh);
    const float* bias = (sel == 0) ? bq : ((sel == 1) ? bk : bv);
    __half* out       = (sel == 0) ? g_q : ((sel == 1) ? g_k : g_v);
    const float osc   = (sel == 0) ? QSC : 1.0f;

    const int row0 = blockIdx.x * 128;

    float acc[2][8][4] = {};
    auto bsrc = [&](int k, int c8) {
        return W + ((size_t)h * DM + k) * DH + c8 * 8;
    };
    gemm128x64(g_xh + (size_t)row0 * DM, bsrc, DM/64, As, Bs, acc);

    const int tid = threadIdx.x, lane = tid & 31, wid = tid >> 5;
    const int lq = lane >> 2, lr = lane & 3;

    #pragma unroll
    for (int mt = 0; mt < 2; mt++) {
        #pragma unroll
        for (int nt = 0; nt < 8; nt++) {
            int d = nt*8 + 2*lr;
            float bz0 = bias[h*DH + d], bz1 = bias[h*DH + d + 1];
            #pragma unroll
            for (int half_ = 0; half_ < 2; half_++) {
                int gr = row0 + wid*32 + mt*16 + lq + half_*8;
                int bb = gr / SEQ, s = gr % SEQ;
                size_t base = (((size_t)bb*NH + h)*SEQ + s)*DH + d;
                *(__half2*)(out + base) = __floats2half2_rn(
                    (acc[mt][nt][half_*2+0] + bz0) * osc,
                    (acc[mt][nt][half_*2+1] + bz1) * osc);
            }
        }
    }
}

// ---------------------------------------------------------------------------
// Kernel 3: output projection. grid=(ROWS/128, 12), block=128. fp32 out.
// ---------------------------------------------------------------------------
__global__ void __launch_bounds__(128, 4) oproj_kernel(
    const float* __restrict__ bo, float* __restrict__ out)
{
    extern __shared__ __half smh[];
    __half* As = smh;
    __half* Bs = smh + 2*A_STh;

    const int row0 = blockIdx.x * 128;
    const int n0   = blockIdx.y * 64;

    float acc[2][8][4] = {};
    auto bsrc = [&](int k, int c8) {
        return g_woh + (size_t)k * DM + n0 + c8 * 8;
    };
    gemm128x64(g_zh + (size_t)row0 * DM, bsrc, DM/64, As, Bs, acc);

    const int tid = threadIdx.x, lane = tid & 31, wid = tid >> 5;
    const int lq = lane >> 2, lr = lane & 3;

    #pragma unroll
    for (int mt = 0; mt < 2; mt++) {
        #pragma unroll
        for (int nt = 0; nt < 8; nt++) {
            int c = n0 + nt*8 + 2*lr;
            float bz0 = bo[c], bz1 = bo[c + 1];
            #pragma unroll
            for (int half_ = 0; half_ < 2; half_++) {
                size_t orow = (size_t)(row0 + wid*32 + mt*16 + lq + half_*8) * DM;
                out[orow + c]     = acc[mt][nt][half_*2+0] + bz0;
                out[orow + c + 1] = acc[mt][nt][half_*2+1] + bz1;
            }
        }
    }
}

// ===========================================================================
// Kernel 2: causal flash attention — exact R13 configuration (best measured):
// register-resident Q+P, plain __launch_bounds__(128), 3-stage cp.async.
// ===========================================================================
#define QTILE 128
#define PHp 72
#define KVST (64*PHp)
#define STG (2*KVST)
#define KV_OFF (QTILE*PHp)
#define FLASH_SMEM ((QTILE*PHp + 3*STG) * 2)

__global__ void __launch_bounds__(128) flash_kernel()
{
    extern __shared__ __half smh[];
    __half* Qs = smh;

    const int qt = (int)gridDim.x - 1 - (int)blockIdx.x;
    const int h  = blockIdx.y;
    const int b  = blockIdx.z;
    const int q0 = qt * QTILE;

    const size_t hb = ((size_t)b * NH + h) * SEQ * DH;
    const __half* qp = g_q + hb;
    const __half* kp = g_k + hb;
    const __half* vp = g_v + hb;

    const int tid  = threadIdx.x;
    const int lane = tid & 31;
    const int wid  = tid >> 5;
    const int lq   = lane >> 2, lr = lane & 3;
    const int lrow = lane & 15, lch = (lane >> 4) * 8;
    const int j8 = lane >> 3, i8 = lane & 7;
    const int wbase = wid * 32;

    auto loadKV = [&](int kt, int s) {
        int k0 = kt * 64;
        #pragma unroll
        for (int i = 0; i < 4; i++) {
            int id = tid + i * 128;
            int r = id >> 3, c8 = id & 7;
            CPA(su32(&smh[KV_OFF + s*STG + r*PHp + c8*8]),        kp + (size_t)(k0+r)*DH + c8*8);
            CPA(su32(&smh[KV_OFF + s*STG + KVST + r*PHp + c8*8]), vp + (size_t)(k0+r)*DH + c8*8);
        }
    };

    #pragma unroll
    for (int i = 0; i < 8; i++) {
        int id = tid + i * 128;
        int r = id >> 3, c8 = id & 7;
        CPA(su32(&Qs[r*PHp + c8*8]), qp + (size_t)(q0+r)*DH + c8*8);
    }
    loadKV(0, 0);
    CPC();
    const int nkt = 2*qt + 2;
    if (nkt > 1) loadKV(1, 1);
    CPC();

    CPW1();
    __syncthreads();

    uint32_t qa[2][4][4];
    #pragma unroll
    for (int mt = 0; mt < 2; mt++)
        #pragma unroll
        for (int kc = 0; kc < 4; kc++)
            ldsm4(qa[mt][kc], su32(&Qs[(wbase + mt*16 + lrow)*PHp + kc*16 + lch]));

    float o[2][8][4] = {};
    float mrow[2][2], lrow2[2][2];
    #pragma unroll
    for (int mt = 0; mt < 2; mt++) { mrow[mt][0]=-INFINITY; mrow[mt][1]=-INFINITY; lrow2[mt][0]=0.f; lrow2[mt][1]=0.f; }

    for (int kt = 0; kt < nkt; kt++) {
        if (kt > 0) {
            if (kt + 1 < nkt) { CPW1(); } else { CPW0(); }
            __syncthreads();
        }
        if (kt + 2 < nkt) { loadKV(kt + 2, (kt + 2) % 3); CPC(); }

        const int k0 = kt * 64;
        const __half* K_ = smh + KV_OFF + (kt % 3) * STG;
        const __half* V_ = K_ + KVST;

        float sf[2][8][4] = {};
        #pragma unroll
        for (int kc = 0; kc < 4; kc++) {
            uint32_t bk2[8][2];
            #pragma unroll
            for (int ntp = 0; ntp < 4; ntp++) {
                uint32_t r4[4];
                ldsm4(r4, su32(&K_[(ntp*16 + (j8>>1)*8 + i8)*PHp + kc*16 + (j8&1)*8]));
                bk2[2*ntp][0]   = r4[0]; bk2[2*ntp][1]   = r4[1];
                bk2[2*ntp+1][0] = r4[2]; bk2[2*ntp+1][1] = r4[3];
            }
            #pragma unroll
            for (int nt = 0; nt < 8; nt++) {
                mma16(sf[0][nt], qa[0][kc], bk2[nt]);
                mma16(sf[1][nt], qa[1][kc], bk2[nt]);
            }
        }

        const bool nm = (k0 + 63 > q0 + wbase);
        if (nm) {
            #pragma unroll
            for (int mt = 0; mt < 2; mt++) {
                int grow0 = q0 + wbase + mt*16 + lq;
                #pragma unroll
                for (int nt = 0; nt < 8; nt++) {
                    #pragma unroll
                    for (int e = 0; e < 4; e++) {
                        int gc = k0 + nt*8 + 2*lr + (e & 1);
                        int grow = grow0 + ((e >= 2) ? 8 : 0);
                        if (gc > grow) sf[mt][nt][e] = -1e30f;
                    }
                }
            }
        }

        uint32_t plo[2][8], phi[2][8];
        #pragma unroll
        for (int mt = 0; mt < 2; mt++) {
            float t0 = -INFINITY, t1 = -INFINITY;
            #pragma unroll
            for (int nt = 0; nt < 8; nt++) {
                t0 = fmaxf(t0, fmaxf(sf[mt][nt][0], sf[mt][nt][1]));
                t1 = fmaxf(t1, fmaxf(sf[mt][nt][2], sf[mt][nt][3]));
            }
            t0 = fmaxf(t0, __shfl_xor_sync(0xffffffffu, t0, 1));
            t0 = fmaxf(t0, __shfl_xor_sync(0xffffffffu, t0, 2));
            t1 = fmaxf(t1, __shfl_xor_sync(0xffffffffu, t1, 1));
            t1 = fmaxf(t1, __shfl_xor_sync(0xffffffffu, t1, 2));

            float mn0 = fmaxf(mrow[mt][0], t0), mn1 = fmaxf(mrow[mt][1], t1);
            float sc0 = ex2f(mrow[mt][0] - mn0), sc1 = ex2f(mrow[mt][1] - mn1);
            mrow[mt][0] = mn0; mrow[mt][1] = mn1;

            float s0 = 0.f, s1 = 0.f;
            #pragma unroll
            for (int nt = 0; nt < 8; nt++) {
                float p0 = ex2f(sf[mt][nt][0] - mn0);
                float p1 = ex2f(sf[mt][nt][1] - mn0);
                float p2 = ex2f(sf[mt][nt][2] - mn1);
                float p3 = ex2f(sf[mt][nt][3] - mn1);
                s0 += p0 + p1; s1 += p2 + p3;
                plo[mt][nt] = h2u(__floats2half2_rn(p0, p1));
                phi[mt][nt] = h2u(__floats2half2_rn(p2, p3));
            }
            s0 += __shfl_xor_sync(0xffffffffu, s0, 1);
            s0 += __shfl_xor_sync(0xffffffffu, s0, 2);
            s1 += __shfl_xor_sync(0xffffffffu, s1, 1);
            s1 += __shfl_xor_sync(0xffffffffu, s1, 2);
            lrow2[mt][0] = lrow2[mt][0] * sc0 + s0;
            lrow2[mt][1] = lrow2[mt][1] * sc1 + s1;

            #pragma unroll
            for (int nt = 0; nt < 8; nt++) {
                o[mt][nt][0] *= sc0; o[mt][nt][1] *= sc0;
                o[mt][nt][2] *= sc1; o[mt][nt][3] *= sc1;
            }
        }

        #pragma unroll
        for (int kc = 0; kc < 4; kc++) {
            uint32_t bv2[8][2];
            #pragma unroll
            for (int dp = 0; dp < 4; dp++) {
                uint32_t r4[4];
                ldsm4t(r4, su32(&V_[(kc*16 + (j8&1)*8 + i8)*PHp + dp*16 + (j8>>1)*8]));
                bv2[2*dp][0]   = r4[0]; bv2[2*dp][1]   = r4[1];
                bv2[2*dp+1][0] = r4[2]; bv2[2*dp+1][1] = r4[3];
            }
            #pragma unroll
            for (int mt = 0; mt < 2; mt++) {
                uint32_t a[4] = { plo[mt][2*kc], phi[mt][2*kc],
                                  plo[mt][2*kc+1], phi[mt][2*kc+1] };
                #pragma unroll
                for (int nt = 0; nt < 8; nt++)
                    mma16(o[mt][nt], a, bv2[nt]);
            }
        }
    }

    #pragma unroll
    for (int mt = 0; mt < 2; mt++) {
        float inv0 = 1.f / lrow2[mt][0], inv1 = 1.f / lrow2[mt][1];
        size_t r0 = (size_t)b * SEQ + q0 + wbase + mt*16 + lq;
        #pragma unroll
        for (int nt = 0; nt < 8; nt++) {
            int col = h*DH + nt*8 + 2*lr;
            *(__half2*)&g_zh[r0 * DM + col] =
                __floats2half2_rn(o[mt][nt][0] * inv0, o[mt][nt][1] * inv0);
            *(__half2*)&g_zh[(r0 + 8) * DM + col] =
                __floats2half2_rn(o[mt][nt][2] * inv1, o[mt][nt][3] * inv1);
        }
    }
}

extern "C" void kernel_launch(void* const* d_in, const int* in_sizes, int n_in,
                              void* d_out, int out_size)
{
    const float* x  = (const float*)d_in[0];
    const float* Wq = (const float*)d_in[1];
    const float* Wk = (const float*)d_in[2];
    const float* Wv = (const float*)d_in[3];
    const float* Wo = (const float*)d_in[4];
    const float* bq = (const float*)d_in[5];
    const float* bk = (const float*)d_in[6];
    const float* bv = (const float*)d_in[7];
    const float* bo = (const float*)d_in[8];
    float* out = (float*)d_out;

    cudaFuncSetAttribute(qkv_kernel,   cudaFuncAttributeMaxDynamicSharedMemorySize, GEMM_SMEM);
    cudaFuncSetAttribute(oproj_kernel, cudaFuncAttributeMaxDynamicSharedMemorySize, GEMM_SMEM);
    cudaFuncSetAttribute(flash_kernel, cudaFuncAttributeMaxDynamicSharedMemorySize, FLASH_SMEM);

    cvt_all_kernel<<<(CVT_TOTAL + 255)/256, 256>>>(
        (const float4*)x, (const float4*)Wq, (const float4*)Wk,
        (const float4*)Wv, (const float4*)Wo);

    qkv_kernel<<<dim3(ROWS/128, 36), 128, GEMM_SMEM>>>(bq, bk, bv);
    flash_kernel<<<dim3(SEQ/QTILE, NH, BATCH), 128, FLASH_SMEM>>>();
    oproj_kernel<<<dim3(ROWS/128, 12), 128, GEMM_SMEM>>>(bo, out);
}